// round 2
// baseline (speedup 1.0000x reference)
#include <cuda_runtime.h>

// YOLOv3 detection-head decode, fused single pass.
// Input  x:       [bs, 3*85, 76, 76] fp32
//        anchors: [3, 2] fp32 (already scaled by 1/img_size)
// Output (concatenated, fp32):
//        pred:  [bs, 3, 76, 76, 7]  = x1,y1,x2,y2,conf,cls_score,cls_idx  (all * valid)
//        valid: [bs, 3, 76, 76]     as 0.0/1.0
//
// Key algebraic simplification: sigmoid is monotonic, so
//   max(sigmoid(cls)) == sigmoid(max(cls)), argmax(sigmoid(cls)) == argmax(cls).
// -> only 4 sigmoids + 2 exps per cell instead of 83 sigmoids. Kernel is HBM-bound.

#define HWV     5776      // 76*76
#define WV      76
#define HV      76
#define ATTRS   85
#define NCLS    80
#define NMASK   3
#define VAL_CONF 0.1f

__device__ __forceinline__ float sigmoidf(float v) {
    return 1.0f / (1.0f + __expf(-v));
}

__global__ void __launch_bounds__(256)
yolo_head_kernel(const float* __restrict__ x,
                 const float* __restrict__ anchors,
                 float* __restrict__ out,
                 int nplanes,            // bs * NMASK
                 long long pred_elems)   // nplanes * HWV * 7
{
    const int QPP = HWV / 4;            // 1444 quads per plane
    int g = blockIdx.x * blockDim.x + threadIdx.x;
    int NG = nplanes * QPP;
    if (g >= NG) return;

    int plane = g / QPP;
    int q     = g - plane * QPP;        // quad index within plane
    int m     = plane % NMASK;          // anchor/mask index
    int h     = q / (WV / 4);           // 0..75
    int w0    = (q - h * (WV / 4)) * 4; // 0,4,...,72

    const float* p = x + (size_t)plane * (ATTRS * HWV) + (size_t)q * 4;

    // Attributes 0..4 (tx, ty, tw, th, conf) — each a coalesced float4 stream.
    float4 ftx = *(const float4*)(p + 0 * HWV);
    float4 fty = *(const float4*)(p + 1 * HWV);
    float4 ftw = *(const float4*)(p + 2 * HWV);
    float4 fth = *(const float4*)(p + 3 * HWV);
    float4 ftc = *(const float4*)(p + 4 * HWV);

    float txa[4] = {ftx.x, ftx.y, ftx.z, ftx.w};
    float tya[4] = {fty.x, fty.y, fty.z, fty.w};
    float twa[4] = {ftw.x, ftw.y, ftw.z, ftw.w};
    float tha[4] = {fth.x, fth.y, fth.z, fth.w};
    float tca[4] = {ftc.x, ftc.y, ftc.z, ftc.w};

    // Class max/argmax over raw logits (strict '>' keeps first-occurrence
    // tie-break, matching jnp.argmax).
    float best[4];
    int   bidx[4];
    {
        float4 v = *(const float4*)(p + 5 * HWV);
        best[0] = v.x; best[1] = v.y; best[2] = v.z; best[3] = v.w;
        bidx[0] = 0; bidx[1] = 0; bidx[2] = 0; bidx[3] = 0;
    }
    #pragma unroll 5
    for (int a = 1; a < NCLS; a++) {
        float4 v = *(const float4*)(p + (size_t)(5 + a) * HWV);
        float vv[4] = {v.x, v.y, v.z, v.w};
        #pragma unroll
        for (int j = 0; j < 4; j++) {
            if (vv[j] > best[j]) { best[j] = vv[j]; bidx[j] = a; }
        }
    }

    float aw = __ldg(&anchors[2 * m + 0]);
    float ah = __ldg(&anchors[2 * m + 1]);

    const float invW = 1.0f / (float)WV;
    const float invH = 1.0f / (float)HV;

    long long cell0 = (long long)plane * HWV + (long long)q * 4;

    #pragma unroll
    for (int j = 0; j < 4; j++) {
        float cx   = (sigmoidf(txa[j]) + (float)(w0 + j)) * invW;
        float cy   = (sigmoidf(tya[j]) + (float)h)        * invH;
        float bw   = __expf(twa[j]) * aw;
        float bh   = __expf(tha[j]) * ah;
        float conf = sigmoidf(tca[j]);
        float cls  = sigmoidf(best[j]);
        float s    = (conf > VAL_CONF) ? 1.0f : 0.0f;

        float* o = out + (cell0 + j) * 7;
        o[0] = (cx - bw * 0.5f) * s;
        o[1] = (cy - bh * 0.5f) * s;
        o[2] = (cx + bw * 0.5f) * s;
        o[3] = (cy + bh * 0.5f) * s;
        o[4] = conf * s;
        o[5] = cls * s;
        o[6] = (float)bidx[j] * s;

        out[pred_elems + cell0 + j] = s;
    }
}

extern "C" void kernel_launch(void* const* d_in, const int* in_sizes, int n_in,
                              void* d_out, int out_size)
{
    const float* x       = (const float*)d_in[0];
    const float* anchors = (const float*)d_in[1];
    float*       out     = (float*)d_out;

    int nplanes = in_sizes[0] / (ATTRS * HWV);          // bs * 3
    long long pred_elems = (long long)nplanes * HWV * 7;

    int NG    = nplanes * (HWV / 4);
    int block = 256;
    int grid  = (NG + block - 1) / block;
    yolo_head_kernel<<<grid, block>>>(x, anchors, out, nplanes, pred_elems);
}

// round 3
// speedup vs baseline: 1.6206x; 1.6206x over previous
#include <cuda_runtime.h>

// YOLOv3 detection-head decode, fused single pass. One thread per cell.
//
// R2 -> R3 change: previous kernel used 1 thread per 4 cells (float4 loads),
// giving only 271 CTAs -> 22% occupancy -> latency-bound at 34% DRAM.
// Scalar-per-cell quadruples the grid (1083 CTAs, ~58 warps/SM) while keeping
// perfect coalescing (32 lanes x consecutive cells = 128B/request), and the
// unroll-16 class loop gives per-warp MLP ~16.
//
// Algebraic simplification: sigmoid is monotonic ->
//   max(sigmoid(cls)) == sigmoid(max(cls)), argmax(sigmoid(cls)) == argmax(cls).

#define HWV     5776      // 76*76
#define WV      76
#define HV      76
#define ATTRS   85
#define NCLS    80
#define NMASK   3
#define VAL_CONF 0.1f

__device__ __forceinline__ float sigmoidf(float v) {
    return 1.0f / (1.0f + __expf(-v));
}

__global__ void __launch_bounds__(256)
yolo_head_kernel(const float* __restrict__ x,
                 const float* __restrict__ anchors,
                 float* __restrict__ out,
                 int ncells,             // nplanes * HWV
                 long long pred_elems)   // nplanes * HWV * 7
{
    int g = blockIdx.x * blockDim.x + threadIdx.x;
    if (g >= ncells) return;

    int plane = g / HWV;
    int idx   = g - plane * HWV;        // cell index within plane
    int m     = plane % NMASK;          // anchor/mask index
    int h     = idx / WV;
    int w     = idx - h * WV;

    const float* p = x + (size_t)plane * (ATTRS * HWV) + idx;

    // Attributes 0..4 (tx, ty, tw, th, conf) — independent coalesced streams.
    float tx = p[0 * HWV];
    float ty = p[1 * HWV];
    float tw = p[2 * HWV];
    float th = p[3 * HWV];
    float tc = p[4 * HWV];

    // Class max/argmax over raw logits. Strict '>' keeps first-occurrence
    // tie-break, matching jnp.argmax. Unroll 16 -> ptxas front-batches 16
    // independent LDGs per iteration group (high MLP).
    float best = p[5 * HWV];
    int   bidx = 0;
    #pragma unroll 16
    for (int a = 1; a < NCLS; a++) {
        float v = p[(size_t)(5 + a) * HWV];
        if (v > best) { best = v; bidx = a; }
    }

    float aw = __ldg(&anchors[2 * m + 0]);
    float ah = __ldg(&anchors[2 * m + 1]);

    const float invW = 1.0f / (float)WV;
    const float invH = 1.0f / (float)HV;

    float cx   = (sigmoidf(tx) + (float)w) * invW;
    float cy   = (sigmoidf(ty) + (float)h) * invH;
    float bw   = __expf(tw) * aw;
    float bh   = __expf(th) * ah;
    float conf = sigmoidf(tc);
    float cls  = sigmoidf(best);
    float s    = (conf > VAL_CONF) ? 1.0f : 0.0f;

    float* o = out + (long long)g * 7;
    o[0] = (cx - bw * 0.5f) * s;
    o[1] = (cy - bh * 0.5f) * s;
    o[2] = (cx + bw * 0.5f) * s;
    o[3] = (cy + bh * 0.5f) * s;
    o[4] = conf * s;
    o[5] = cls * s;
    o[6] = (float)bidx * s;

    out[pred_elems + g] = s;
}

extern "C" void kernel_launch(void* const* d_in, const int* in_sizes, int n_in,
                              void* d_out, int out_size)
{
    const float* x       = (const float*)d_in[0];
    const float* anchors = (const float*)d_in[1];
    float*       out     = (float*)d_out;

    int nplanes = in_sizes[0] / (ATTRS * HWV);          // bs * 3
    int ncells  = nplanes * HWV;
    long long pred_elems = (long long)ncells * 7;

    int block = 256;
    int grid  = (ncells + block - 1) / block;
    yolo_head_kernel<<<grid, block>>>(x, anchors, out, ncells, pred_elems);
}

// round 4
// speedup vs baseline: 1.7796x; 1.0981x over previous
#include <cuda_runtime.h>

// YOLOv3 detection-head decode, fused single pass. One thread per cell.
//
// R3 -> R4:
//  - class argmax split into 4 independent chains (4x ILP on the reduction),
//    merged with an exact first-occurrence tie-break.
//  - pred stores staged through smem and written as coalesced float4:
//    49 store wavefronts/warp -> 7.
//  - __stcs (evict-first) on outputs so the 94MB input stays L2-resident
//    across graph replays (total footprint ~103MB < 126MB L2).
//
// Algebraic simplification: sigmoid is monotonic ->
//   max(sigmoid(cls)) == sigmoid(max(cls)), argmax(sigmoid(cls)) == argmax(cls).

#define HWV     5776      // 76*76
#define WV      76
#define HV      76
#define ATTRS   85
#define NCLS    80
#define NMASK   3
#define VAL_CONF 0.1f

__device__ __forceinline__ float sigmoidf(float v) {
    return 1.0f / (1.0f + __expf(-v));
}

__global__ void __launch_bounds__(256)
yolo_head_kernel(const float* __restrict__ x,
                 const float* __restrict__ anchors,
                 float* __restrict__ out,
                 int ncells,             // nplanes * HWV
                 long long pred_elems)   // nplanes * HWV * 7
{
    __shared__ float sp[8][224];        // per-warp staging: 32 cells x 7 attrs

    int g    = blockIdx.x * blockDim.x + threadIdx.x;
    int lane = threadIdx.x & 31;
    int wrp  = threadIdx.x >> 5;
    bool active = (g < ncells);

    int plane = g / HWV;
    int idx   = g - plane * HWV;        // cell index within plane
    int m     = plane % NMASK;          // anchor/mask index
    int h     = idx / WV;
    int w     = idx - h * WV;

    const float* p = x + (size_t)plane * (ATTRS * HWV) + idx;

    float tx = 0.f, ty = 0.f, tw = 0.f, th = 0.f, tc = 0.f;
    float b0 = 0.f, b1 = 0.f, b2 = 0.f, b3 = 0.f;
    int   i0 = 0,  i1 = 1,  i2 = 2,  i3 = 3;

    if (active) {
        // Attributes 0..4 (tx, ty, tw, th, conf) — independent coalesced streams.
        tx = p[0 * HWV];
        ty = p[1 * HWV];
        tw = p[2 * HWV];
        th = p[3 * HWV];
        tc = p[4 * HWV];

        // Class max/argmax over raw logits, 4 independent chains.
        b0 = p[5 * HWV];
        b1 = p[6 * HWV];
        b2 = p[7 * HWV];
        b3 = p[8 * HWV];
        #pragma unroll 4
        for (int a = 4; a < NCLS; a += 4) {
            float v0 = p[(size_t)(5 + a) * HWV];
            float v1 = p[(size_t)(6 + a) * HWV];
            float v2 = p[(size_t)(7 + a) * HWV];
            float v3 = p[(size_t)(8 + a) * HWV];
            if (v0 > b0) { b0 = v0; i0 = a;     }
            if (v1 > b1) { b1 = v1; i1 = a + 1; }
            if (v2 > b2) { b2 = v2; i2 = a + 2; }
            if (v3 > b3) { b3 = v3; i3 = a + 3; }
        }
    }

    // Exact first-occurrence merge (matches jnp.argmax tie-break):
    // prefer the candidate with strictly larger value, or equal value and
    // strictly smaller index.
    float best = b0; int bidx = i0;
    if (b1 > best || (b1 == best && i1 < bidx)) { best = b1; bidx = i1; }
    if (b2 > best || (b2 == best && i2 < bidx)) { best = b2; bidx = i2; }
    if (b3 > best || (b3 == best && i3 < bidx)) { best = b3; bidx = i3; }

    float aw = __ldg(&anchors[2 * m + 0]);
    float ah = __ldg(&anchors[2 * m + 1]);

    const float invW = 1.0f / (float)WV;
    const float invH = 1.0f / (float)HV;

    float cx   = (sigmoidf(tx) + (float)w) * invW;
    float cy   = (sigmoidf(ty) + (float)h) * invH;
    float bw   = __expf(tw) * aw;
    float bh   = __expf(th) * ah;
    float conf = sigmoidf(tc);
    float cls  = sigmoidf(best);
    float s    = (conf > VAL_CONF) ? 1.0f : 0.0f;

    // Stage 7 outputs in smem (stride-7 writes: gcd(7,32)=1 -> conflict-free).
    float* sw_ = sp[wrp];
    sw_[lane * 7 + 0] = (cx - bw * 0.5f) * s;
    sw_[lane * 7 + 1] = (cy - bh * 0.5f) * s;
    sw_[lane * 7 + 2] = (cx + bw * 0.5f) * s;
    sw_[lane * 7 + 3] = (cy + bh * 0.5f) * s;
    sw_[lane * 7 + 4] = conf * s;
    sw_[lane * 7 + 5] = cls * s;
    sw_[lane * 7 + 6] = (float)bidx * s;
    __syncwarp();

    // Coalesced float4 writeback of the warp's contiguous 896B pred region.
    // Warp base = (first cell of warp)*7 floats; 896 = 7*128 -> 128B aligned.
    int gbase = g - lane;               // first cell of this warp
    if (gbase < ncells) {
        float* obase = out + (long long)gbase * 7;
        #pragma unroll
        for (int j = lane; j < 56; j += 32) {
            float4 v = *(const float4*)&sw_[j * 4];
            __stcs((float4*)(obase + j * 4), v);
        }
    }

    if (active) __stcs(&out[pred_elems + g], s);
}

extern "C" void kernel_launch(void* const* d_in, const int* in_sizes, int n_in,
                              void* d_out, int out_size)
{
    const float* x       = (const float*)d_in[0];
    const float* anchors = (const float*)d_in[1];
    float*       out     = (float*)d_out;

    int nplanes = in_sizes[0] / (ATTRS * HWV);          // bs * 3
    int ncells  = nplanes * HWV;
    long long pred_elems = (long long)ncells * 7;

    int block = 256;
    int grid  = (ncells + block - 1) / block;           // 1083, no tail
    yolo_head_kernel<<<grid, block>>>(x, anchors, out, ncells, pred_elems);
}

// round 5
// speedup vs baseline: 1.8696x; 1.0506x over previous
#include <cuda_runtime.h>
#include <float.h>

// YOLOv3 detection-head decode, fused single pass. One thread per cell.
//
// R4 -> R5: trade occupancy for MLP. regs was pinned at 31 (full-occupancy
// ceiling), which prevented ptxas from front-batching the class loads ->
// MLP ~6-8, latency-exposed (issue 25.5%, DRAM 55%, nothing saturated).
// Now: __launch_bounds__(256,6) (~42-reg budget) + explicit 16-deep register
// load buffer per class batch -> guaranteed per-warp MLP=16,
// outstanding/SM ~ 48 warps * 16 = 768 >> ~170 needed for the BW-delay product.
//
// Algebraic simplification: sigmoid is monotonic ->
//   max(sigmoid(cls)) == sigmoid(max(cls)), argmax(sigmoid(cls)) == argmax(cls).

#define HWV     5776      // 76*76
#define WV      76
#define HV      76
#define ATTRS   85
#define NCLS    80
#define NMASK   3
#define VAL_CONF 0.1f

__device__ __forceinline__ float sigmoidf(float v) {
    return 1.0f / (1.0f + __expf(-v));
}

__global__ void __launch_bounds__(256, 6)
yolo_head_kernel(const float* __restrict__ x,
                 const float* __restrict__ anchors,
                 float* __restrict__ out,
                 int ncells,             // nplanes * HWV
                 long long pred_elems)   // nplanes * HWV * 7
{
    __shared__ float sp[8][224];        // per-warp staging: 32 cells x 7 attrs

    int g    = blockIdx.x * blockDim.x + threadIdx.x;
    int lane = threadIdx.x & 31;
    int wrp  = threadIdx.x >> 5;
    bool active = (g < ncells);
    int gc = active ? g : (ncells - 1);  // clamp: inactive lanes do safe loads

    int plane = gc / HWV;
    int idx   = gc - plane * HWV;       // cell index within plane
    int m     = plane % NMASK;          // anchor/mask index
    int h     = idx / WV;
    int w     = idx - h * WV;

    const float* p = x + (size_t)plane * (ATTRS * HWV) + idx;

    // Attributes 0..4 — independent coalesced streams, issued up front.
    float tx = p[0 * HWV];
    float ty = p[1 * HWV];
    float tw = p[2 * HWV];
    float th = p[3 * HWV];
    float tc = p[4 * HWV];

    // Class max/argmax over raw logits. Batches of 16 loads land in a
    // register buffer BEFORE any compare consumes them -> MLP=16 per batch.
    // 4 independent compare chains (class index mod 4) for ALU ILP; strict '>'
    // keeps first occurrence within each chain.
    float b0 = -FLT_MAX, b1 = -FLT_MAX, b2 = -FLT_MAX, b3 = -FLT_MAX;
    int   i0 = 0, i1 = 0, i2 = 0, i3 = 0;

    #pragma unroll
    for (int a0 = 0; a0 < NCLS; a0 += 16) {
        float v[16];
        #pragma unroll
        for (int j = 0; j < 16; j++)
            v[j] = p[(size_t)(5 + a0 + j) * HWV];
        #pragma unroll
        for (int j = 0; j < 16; j += 4) {
            int a = a0 + j;
            if (v[j + 0] > b0) { b0 = v[j + 0]; i0 = a;     }
            if (v[j + 1] > b1) { b1 = v[j + 1]; i1 = a + 1; }
            if (v[j + 2] > b2) { b2 = v[j + 2]; i2 = a + 2; }
            if (v[j + 3] > b3) { b3 = v[j + 3]; i3 = a + 3; }
        }
    }

    // Exact first-occurrence merge (matches jnp.argmax tie-break).
    float best = b0; int bidx = i0;
    if (b1 > best || (b1 == best && i1 < bidx)) { best = b1; bidx = i1; }
    if (b2 > best || (b2 == best && i2 < bidx)) { best = b2; bidx = i2; }
    if (b3 > best || (b3 == best && i3 < bidx)) { best = b3; bidx = i3; }

    float aw = __ldg(&anchors[2 * m + 0]);
    float ah = __ldg(&anchors[2 * m + 1]);

    const float invW = 1.0f / (float)WV;
    const float invH = 1.0f / (float)HV;

    float cx   = (sigmoidf(tx) + (float)w) * invW;
    float cy   = (sigmoidf(ty) + (float)h) * invH;
    float bw   = __expf(tw) * aw;
    float bh   = __expf(th) * ah;
    float conf = sigmoidf(tc);
    float cls  = sigmoidf(best);
    float s    = (conf > VAL_CONF) ? 1.0f : 0.0f;

    // Stage 7 outputs in smem (stride-7: gcd(7,32)=1 -> conflict-free).
    float* sw_ = sp[wrp];
    sw_[lane * 7 + 0] = (cx - bw * 0.5f) * s;
    sw_[lane * 7 + 1] = (cy - bh * 0.5f) * s;
    sw_[lane * 7 + 2] = (cx + bw * 0.5f) * s;
    sw_[lane * 7 + 3] = (cy + bh * 0.5f) * s;
    sw_[lane * 7 + 4] = conf * s;
    sw_[lane * 7 + 5] = cls * s;
    sw_[lane * 7 + 6] = (float)bidx * s;
    __syncwarp();

    // Coalesced float4 writeback of the warp's contiguous 896B pred region.
    int gbase = g - lane;               // first cell of this warp
    if (gbase < ncells) {
        float* obase = out + (long long)gbase * 7;
        #pragma unroll
        for (int j = lane; j < 56; j += 32) {
            float4 v4 = *(const float4*)&sw_[j * 4];
            __stcs((float4*)(obase + j * 4), v4);
        }
    }

    if (active) __stcs(&out[pred_elems + g], s);
}

extern "C" void kernel_launch(void* const* d_in, const int* in_sizes, int n_in,
                              void* d_out, int out_size)
{
    const float* x       = (const float*)d_in[0];
    const float* anchors = (const float*)d_in[1];
    float*       out     = (float*)d_out;

    int nplanes = in_sizes[0] / (ATTRS * HWV);          // bs * 3
    int ncells  = nplanes * HWV;
    long long pred_elems = (long long)ncells * 7;

    int block = 256;
    int grid  = (ncells + block - 1) / block;           // 1083
    yolo_head_kernel<<<grid, block>>>(x, anchors, out, ncells, pred_elems);
}